// round 9
// baseline (speedup 1.0000x reference)
#include <cuda_runtime.h>
#include <cuda_bf16.h>
#include <stdint.h>
#include <math.h>

#define N_NODES 10000
#define N_EDGES 100000
#define F_NODE 128
#define F_EDGE 16
#define HEADS 8
#define OUT_CH 128
#define HC 1024
#define NQK 3328   // 1024 q | 1024 k | 1024 v | 128 skip | 128 g

// ---------------- scratch (device globals) ----------------
__device__ __nv_bfloat16 d_xh[N_NODES * 128];
__device__ __nv_bfloat16 d_qb[N_NODES * HC];
__device__ __nv_bfloat16 d_kb[N_NODES * HC];
__device__ __nv_bfloat16 d_vb[N_NODES * HC];
__device__ __nv_bfloat16 d_Bb[N_NODES * 128];
__device__ __nv_bfloat16 d_Wqh[128 * NQK];
__device__ __nv_bfloat16 d_Wql[128 * NQK];
__device__ __nv_bfloat16 d_Werh[128 * 128];
__device__ __nv_bfloat16 d_Werl[128 * 128];
__device__ float d_biasc[NQK];
__device__ float d_skip[N_NODES * 128];
__device__ float d_g[N_NODES * 128];
__device__ float d_aexp[N_EDGES * HEADS];
__device__ float d_s[N_NODES * HEADS];
__device__ float d_vout[N_NODES * 128];
__device__ float d_B[N_NODES * 128];
__device__ float d_pooled[128];

// ---------------- fused prep: bf16(x) | pack_w(h,l) | bias | wer(h,l) ----------
#define SEG0 (N_NODES * 128)
#define SEG1 (128 * 3200)
#define SEG2 (3200)
#define SEG3 (128 * 128)
#define PREP_TOTAL (SEG0 + SEG1 + SEG2 + SEG3)

__global__ __launch_bounds__(256) void prep_all(
    const float* __restrict__ x, const float* __restrict__ Wq,
    const float* __restrict__ Wk, const float* __restrict__ Wv,
    const float* __restrict__ Ws, const float* __restrict__ bq,
    const float* __restrict__ bk, const float* __restrict__ bv,
    const float* __restrict__ bs, const float* __restrict__ We) {
    int idx = blockIdx.x * 256 + threadIdx.x;
    if (idx < SEG0) {
        d_xh[idx] = __float2bfloat16(x[idx]);
        return;
    }
    idx -= SEG0;
    if (idx < SEG1) {
        int k = idx / 3200, col = idx % 3200;
        float v;
        if (col < 1024) v = Wq[k * HC + col];
        else if (col < 2048) v = Wk[k * HC + col - 1024];
        else if (col < 3072) v = Wv[k * HC + col - 2048];
        else v = Ws[k * 128 + col - 3072];
        __nv_bfloat16 h = __float2bfloat16(v);
        d_Wqh[k * NQK + col] = h;
        d_Wql[k * NQK + col] = __float2bfloat16(v - __bfloat162float(h));
        return;
    }
    idx -= SEG1;
    if (idx < SEG2) {
        float b;
        if (idx < 1024) b = bq[idx];
        else if (idx < 2048) b = bk[idx - 1024];
        else if (idx < 3072) b = bv[idx - 2048];
        else b = bs[idx - 3072];
        d_biasc[idx] = b;
        return;
    }
    idx -= SEG2;
    if (idx < SEG3) {
        int j = idx >> 7, c = idx & 127;
        int h = j >> 4, f = j & 15;
        float v = We[f * HC + h * 128 + c];
        __nv_bfloat16 hh = __float2bfloat16(v);
        d_Werh[idx] = hh;
        d_Werl[idx] = __float2bfloat16(v - __bfloat162float(hh));
    }
}

// ---------------- Wqg = Wq @ Wg (f32, folded g columns) + bg ------------------
__global__ __launch_bounds__(128) void wqg_kernel(const float* __restrict__ Wq,
                                                  const float* __restrict__ bq,
                                                  const float* __restrict__ We) {
    int b = blockIdx.x;
    int j = threadIdx.x;
    int h = j >> 4, f = j & 15;
    if (b < 128) {
        __shared__ float sq[HC];
        for (int i = j; i < HC; i += 128) sq[i] = Wq[b * HC + i];
        __syncthreads();
        const float* wep = &We[f * HC + h * 128];
        const float* qp = &sq[h * 128];
        float acc = 0.f;
#pragma unroll 8
        for (int c = 0; c < 128; c++) acc += qp[c] * wep[c];
        __nv_bfloat16 hh = __float2bfloat16(acc);
        d_Wqh[b * NQK + 3200 + j] = hh;
        d_Wql[b * NQK + 3200 + j] = __float2bfloat16(acc - __bfloat162float(hh));
    } else {
        const float* wep = &We[f * HC + h * 128];
        const float* bp = &bq[h * 128];
        float acc = 0.f;
#pragma unroll 8
        for (int c = 0; c < 128; c++) acc += bp[c] * wep[c];
        d_biasc[3200 + j] = acc;
    }
}

__global__ void split_B() {
    int i = blockIdx.x * 256 + threadIdx.x;
    if (i < N_NODES * 128) d_Bb[i] = __float2bfloat16(d_B[i]);
}

// ---------------- MMA / f32x2 helpers ----------------
__device__ __forceinline__ void ldsm4(uint32_t* r, const void* p) {
    unsigned a = (unsigned)__cvta_generic_to_shared(p);
    asm volatile("ldmatrix.sync.aligned.m8n8.x4.shared.b16 {%0,%1,%2,%3}, [%4];\n"
                 : "=r"(r[0]), "=r"(r[1]), "=r"(r[2]), "=r"(r[3]) : "r"(a));
}
__device__ __forceinline__ void ldsm4t(uint32_t* r, const void* p) {
    unsigned a = (unsigned)__cvta_generic_to_shared(p);
    asm volatile("ldmatrix.sync.aligned.m8n8.x4.trans.shared.b16 {%0,%1,%2,%3}, [%4];\n"
                 : "=r"(r[0]), "=r"(r[1]), "=r"(r[2]), "=r"(r[3]) : "r"(a));
}
__device__ __forceinline__ void mma_bf16(float* c, const uint32_t* a, uint32_t b0,
                                         uint32_t b1) {
    asm volatile(
        "mma.sync.aligned.m16n8k16.row.col.f32.bf16.bf16.f32 "
        "{%0,%1,%2,%3}, {%4,%5,%6,%7}, {%8,%9}, {%0,%1,%2,%3};\n"
        : "+f"(c[0]), "+f"(c[1]), "+f"(c[2]), "+f"(c[3])
        : "r"(a[0]), "r"(a[1]), "r"(a[2]), "r"(a[3]), "r"(b0), "r"(b1));
}
__device__ __forceinline__ void cp16(void* sdst, const void* gsrc, bool pred) {
    unsigned s = (unsigned)__cvta_generic_to_shared(sdst);
    int sz = pred ? 16 : 0;
    asm volatile("cp.async.cg.shared.global [%0], [%1], 16, %2;\n" ::"r"(s), "l"(gsrc),
                 "r"(sz));
}
__device__ __forceinline__ unsigned long long bf2f2(uint32_t u) {
    unsigned long long r;
    uint32_t lo = u << 16;
    uint32_t hi = u & 0xFFFF0000u;
    asm("mov.b64 %0, {%1,%2};" : "=l"(r) : "r"(lo), "r"(hi));
    return r;
}
__device__ __forceinline__ unsigned long long fma2(unsigned long long a,
                                                   unsigned long long b,
                                                   unsigned long long c) {
    unsigned long long d;
    asm("fma.rn.f32x2 %0, %1, %2, %3;" : "=l"(d) : "l"(a), "l"(b), "l"(c));
    return d;
}
__device__ __forceinline__ unsigned long long pack2(float x, float y) {
    unsigned long long r;
    asm("mov.b64 %0, {%1,%2};" : "=l"(r) : "f"(x), "f"(y));
    return r;
}
__device__ __forceinline__ float2 up2(unsigned long long v) {
    float2 r;
    asm("mov.b64 {%0,%1}, %2;" : "=f"(r.x), "=f"(r.y) : "l"(v));
    return r;
}

// ---------------- unified TC GEMM, double-buffered, 2-pass W-split ----------------
__global__ __launch_bounds__(256) void gemm_tc(int asel, int wsel, int osel, int M,
                                               int N, int Kstride, int kcount) {
    const __nv_bfloat16* Ah = (asel == 0) ? d_xh : d_Bb;
    const __nv_bfloat16* Wh = (wsel == 0) ? d_Wqh : d_Werh;
    const __nv_bfloat16* Wl = (wsel == 0) ? d_Wql : d_Werl;

    extern __shared__ __align__(16) char dyn[];
    __nv_bfloat16* dynb = (__nv_bfloat16*)dyn;
    float* spool = (float*)(dyn + 38912);

    int tid = threadIdx.x, w = tid >> 5, l = tid & 31;
    int bm = blockIdx.y * 128, bn = blockIdx.x * 64;
    int wm = (w >> 1) * 32, wn = (w & 1) * 32;
    if (osel == 2 && tid < 64) spool[tid] = 0.f;

    float acc[2][4][4];
#pragma unroll
    for (int a = 0; a < 2; a++)
#pragma unroll
        for (int b = 0; b < 4; b++)
#pragma unroll
            for (int c = 0; c < 4; c++) acc[a][b][c] = 0.f;

    int a_r = (l & 7) + ((l >> 3) & 1) * 8;
    int a_ko = ((l >> 4) & 1) * 8;

    auto pA = [&](int st) { return dynb + st * 5120; };
    auto pW = [&](int st, int p) { return dynb + 10240 + (st * 2 + p) * 2304; };

    auto load_stage = [&](int st, int kc) {
        __nv_bfloat16* dstA = pA(st);
#pragma unroll
        for (int i = 0; i < 2; i++) {
            int idx = tid + 256 * i;
            int row = idx >> 2, ch = idx & 3;
            int gr = bm + row;
            cp16(dstA + row * 40 + ch * 8, Ah + (size_t)gr * Kstride + kc + ch * 8,
                 gr < M);
        }
#pragma unroll
        for (int p = 0; p < 2; p++) {
            const __nv_bfloat16* Ws = p ? Wl : Wh;
            __nv_bfloat16* dst = pW(st, p);
            int k = tid >> 3, ch = tid & 7;
            cp16(dst + k * 72 + ch * 8, Ws + (size_t)(kc + k) * N + bn + ch * 8, true);
        }
        asm volatile("cp.async.commit_group;\n" ::);
    };

    auto compute = [&](int st) {
#pragma unroll
        for (int k16 = 0; k16 < 2; k16++) {
            uint32_t Af[2][4], Bh[2][4], Bl[2][4];
            __nv_bfloat16* ah = pA(st);
#pragma unroll
            for (int mt = 0; mt < 2; mt++)
                ldsm4(Af[mt], ah + (wm + mt * 16 + a_r) * 40 + k16 * 16 + a_ko);
            __nv_bfloat16* wh = pW(st, 0);
            __nv_bfloat16* wl = pW(st, 1);
#pragma unroll
            for (int p = 0; p < 2; p++) {
                ldsm4t(Bh[p], wh + (k16 * 16 + a_r) * 72 + wn + p * 16 + a_ko);
                ldsm4t(Bl[p], wl + (k16 * 16 + a_r) * 72 + wn + p * 16 + a_ko);
            }
#pragma unroll
            for (int nt = 0; nt < 4; nt++) {
                uint32_t bh0 = Bh[nt >> 1][(nt & 1) * 2], bh1 = Bh[nt >> 1][(nt & 1) * 2 + 1];
                uint32_t bl0 = Bl[nt >> 1][(nt & 1) * 2], bl1 = Bl[nt >> 1][(nt & 1) * 2 + 1];
#pragma unroll
                for (int mt = 0; mt < 2; mt++) {
                    mma_bf16(acc[mt][nt], Af[mt], bh0, bh1);
                    mma_bf16(acc[mt][nt], Af[mt], bl0, bl1);
                }
            }
        }
    };

    int nIter = kcount >> 5;
    load_stage(0, 0);
    for (int it = 0; it < nIter; it++) {
        if (it + 1 < nIter) {
            load_stage((it + 1) & 1, (it + 1) * 32);
            asm volatile("cp.async.wait_group 1;\n" ::);
        } else {
            asm volatile("cp.async.wait_group 0;\n" ::);
        }
        __syncthreads();
        compute(it & 1);
        __syncthreads();
    }

    int r0 = l >> 2, cq = (l & 3) * 2;
    if (osel == 0) {
        __nv_bfloat16* dstb = nullptr;
        float* dstf = nullptr;
        int coff;
        if (bn < 1024) { dstb = d_qb; coff = bn; }
        else if (bn < 2048) { dstb = d_kb; coff = bn - 1024; }
        else if (bn < 3072) { dstb = d_vb; coff = bn - 2048; }
        else if (bn < 3200) { dstf = d_skip; coff = bn - 3072; }
        else { dstf = d_g; coff = bn - 3200; }
#pragma unroll
        for (int mt = 0; mt < 2; mt++)
#pragma unroll
            for (int nt = 0; nt < 4; nt++) {
                int gcol = bn + wn + nt * 8 + cq;
                int col = coff + wn + nt * 8 + cq;
                float bb0 = d_biasc[gcol], bb1 = d_biasc[gcol + 1];
#pragma unroll
                for (int rr = 0; rr < 2; rr++) {
                    int row = bm + wm + mt * 16 + r0 + rr * 8;
                    if (row < M) {
                        float v0 = acc[mt][nt][rr * 2] + bb0;
                        float v1 = acc[mt][nt][rr * 2 + 1] + bb1;
                        if (dstf) {
                            dstf[row * 128 + col] = v0;
                            dstf[row * 128 + col + 1] = v1;
                        } else {
                            *(__nv_bfloat162*)&dstb[(size_t)row * HC + col] =
                                __floats2bfloat162_rn(v0, v1);
                        }
                    }
                }
            }
    } else {
#pragma unroll
        for (int nt = 0; nt < 4; nt++) {
            int col = bn + wn + nt * 8 + cq;
            float s0 = 0.f, s1 = 0.f;
#pragma unroll
            for (int mt = 0; mt < 2; mt++)
#pragma unroll
                for (int rr = 0; rr < 2; rr++) {
                    int row = bm + wm + mt * 16 + r0 + rr * 8;
                    if (row < M) {
                        s0 += fmaxf(acc[mt][nt][rr * 2] + d_vout[row * 128 + col] +
                                        d_skip[row * 128 + col], 0.f);
                        s1 += fmaxf(acc[mt][nt][rr * 2 + 1] + d_vout[row * 128 + col + 1] +
                                        d_skip[row * 128 + col + 1], 0.f);
                    }
                }
#pragma unroll
            for (int off = 16; off >= 4; off >>= 1) {
                s0 += __shfl_xor_sync(0xffffffffu, s0, off);
                s1 += __shfl_xor_sync(0xffffffffu, s1, off);
            }
            if (l < 4) {
                atomicAdd(&spool[wn + nt * 8 + cq], s0);
                atomicAdd(&spool[wn + nt * 8 + cq + 1], s1);
            }
        }
        __syncthreads();
        if (tid < 64) atomicAdd(&d_pooled[bn + tid], spool[tid]);
    }
}

// ---------------- edge pass A: alpha, coalesced + f32x2 ----------------
// lane l covers bf16 channels (chunk j)*256 + l*8..+8; chunk partial = head 2j+(l>>4)
__global__ __launch_bounds__(256) void edge_alpha(const float* __restrict__ ea,
                                                  const int* __restrict__ eidx) {
    int e = blockIdx.x * 8 + threadIdx.y;
    if (e >= N_EDGES) return;
    int l = threadIdx.x;
    int src = __ldg(&eidx[e]);
    int dst = __ldg(&eidx[N_EDGES + e]);
    const __nv_bfloat16* qp = &d_qb[(size_t)dst * HC + l * 8];
    const __nv_bfloat16* kp = &d_kb[(size_t)src * HC + l * 8];
    float pd[4];
#pragma unroll
    for (int j = 0; j < 4; j++) {
        uint4 qa = *(const uint4*)(qp + j * 256);   // chunk stride = 256 bf16 channels
        uint4 kb = *(const uint4*)(kp + j * 256);
        unsigned long long a = 0ull;
        a = fma2(bf2f2(qa.x), bf2f2(kb.x), a);
        a = fma2(bf2f2(qa.y), bf2f2(kb.y), a);
        a = fma2(bf2f2(qa.z), bf2f2(kb.z), a);
        a = fma2(bf2f2(qa.w), bf2f2(kb.w), a);
        float2 t = up2(a);
        pd[j] = t.x + t.y;
    }
#pragma unroll
    for (int off = 1; off <= 8; off <<= 1) {
        pd[0] += __shfl_xor_sync(0xffffffffu, pd[0], off);
        pd[1] += __shfl_xor_sync(0xffffffffu, pd[1], off);
        pd[2] += __shfl_xor_sync(0xffffffffu, pd[2], off);
        pd[3] += __shfl_xor_sync(0xffffffffu, pd[3], off);
    }
    // edge term: partial for head l>>2 over f=(l&3)*4..+4
    float4 g4 = *(const float4*)&d_g[dst * 128 + l * 4];
    float4 e4 = *(const float4*)&ea[e * F_EDGE + (l & 3) * 4];
    float et = g4.x * e4.x + g4.y * e4.y + g4.z * e4.z + g4.w * e4.w;
    et += __shfl_xor_sync(0xffffffffu, et, 1);
    et += __shfl_xor_sync(0xffffffffu, et, 2);
    int hsrc = (l & 1) * 16;
    float kd0 = __shfl_sync(0xffffffffu, pd[0], hsrc);
    float kd1 = __shfl_sync(0xffffffffu, pd[1], hsrc);
    float kd2 = __shfl_sync(0xffffffffu, pd[2], hsrc);
    float kd3 = __shfl_sync(0xffffffffu, pd[3], hsrc);
    float etl = __shfl_sync(0xffffffffu, et, (l & 7) * 4);
    if (l < 8) {
        int jj = l >> 1;
        float kd = (jj == 0) ? kd0 : (jj == 1) ? kd1 : (jj == 2) ? kd2 : kd3;
        float aex = __expf((kd + etl) * 0.08838834764831845f);
        d_aexp[e * 8 + l] = aex;
        atomicAdd(&d_s[dst * 8 + l], aex);
    }
}

// ---------------- edge pass B: v-term + B scatter, f32x2 accumulate ----------------
__global__ __launch_bounds__(256) void edge_msg(const float* __restrict__ ea,
                                                const int* __restrict__ eidx) {
    int e = blockIdx.x * 8 + threadIdx.y;
    if (e >= N_EDGES) return;
    int l = threadIdx.x;
    int src = __ldg(&eidx[e]);
    int dst = __ldg(&eidx[N_EDGES + e]);
    float an = 0.f;
    if (l < 8) {
        float s = d_s[dst * 8 + l];
        an = 0.125f * d_aexp[e * 8 + l] / (s + 1e-16f);
    }
    int h2 = l >> 4, c8 = l & 15;
    unsigned long long acc2[4] = {0ull, 0ull, 0ull, 0ull};
#pragma unroll
    for (int hh = 0; hh < 4; hh++) {
        int h = h2 * 4 + hh;
        float anh = __shfl_sync(0xffffffffu, an, h);
        unsigned long long an2 = pack2(anh, anh);
        uint4 vv = *(const uint4*)&d_vb[(size_t)src * HC + h * 128 + c8 * 8];
        acc2[0] = fma2(bf2f2(vv.x), an2, acc2[0]);
        acc2[1] = fma2(bf2f2(vv.y), an2, acc2[1]);
        acc2[2] = fma2(bf2f2(vv.z), an2, acc2[2]);
        acc2[3] = fma2(bf2f2(vv.w), an2, acc2[3]);
    }
    float acc[8];
#pragma unroll
    for (int j = 0; j < 4; j++) {
        float2 t = up2(acc2[j]);
        acc[j * 2] = t.x;
        acc[j * 2 + 1] = t.y;
    }
#pragma unroll
    for (int j = 0; j < 8; j++) acc[j] += __shfl_xor_sync(0xffffffffu, acc[j], 16);
    if (h2 == 0) {
        float* outp = &d_vout[dst * 128 + c8 * 8];
        asm volatile("red.global.add.v4.f32 [%0], {%1,%2,%3,%4};\n" ::"l"(outp),
                     "f"(acc[0]), "f"(acc[1]), "f"(acc[2]), "f"(acc[3])
                     : "memory");
        asm volatile("red.global.add.v4.f32 [%0], {%1,%2,%3,%4};\n" ::"l"(outp + 4),
                     "f"(acc[4]), "f"(acc[5]), "f"(acc[6]), "f"(acc[7])
                     : "memory");
    }
    float4 ea4 = ((const float4*)&ea[e * F_EDGE])[l & 3];
    float anj = __shfl_sync(0xffffffffu, an, l >> 2);
    float* bp = &d_B[dst * 128 + l * 4];
    asm volatile("red.global.add.v4.f32 [%0], {%1,%2,%3,%4};\n" ::"l"(bp),
                 "f"(anj * ea4.x), "f"(anj * ea4.y), "f"(anj * ea4.z), "f"(anj * ea4.w)
                 : "memory");
}

// ---------------- final dot ----------------
__global__ __launch_bounds__(128) void final_dot(const float* __restrict__ Wd,
                                                 const float* __restrict__ bd,
                                                 float* __restrict__ out) {
    int t = threadIdx.x;
    float v = d_pooled[t] * Wd[t];
#pragma unroll
    for (int o = 16; o; o >>= 1) v += __shfl_xor_sync(0xffffffffu, v, o);
    __shared__ float red[4];
    if ((t & 31) == 0) red[t >> 5] = v;
    __syncthreads();
    if (t == 0) out[0] = red[0] + red[1] + red[2] + red[3] + bd[0];
}

extern "C" void kernel_launch(void* const* d_in, const int* in_sizes, int n_in,
                              void* d_out, int out_size) {
    const float* x          = (const float*)d_in[0];
    const float* edge_attr  = (const float*)d_in[1];
    const int*   edge_index = (const int*)d_in[2];
    const float* Wq = (const float*)d_in[3];
    const float* bq = (const float*)d_in[4];
    const float* Wk = (const float*)d_in[5];
    const float* bk = (const float*)d_in[6];
    const float* Wv = (const float*)d_in[7];
    const float* bv = (const float*)d_in[8];
    const float* We = (const float*)d_in[9];
    const float* Wskip = (const float*)d_in[10];
    const float* bskip = (const float*)d_in[11];
    const float* Wd = (const float*)d_in[12];
    const float* bd = (const float*)d_in[13];
    float* out = (float*)d_out;

    static void *p_vout = nullptr, *p_B = nullptr, *p_s = nullptr, *p_pooled = nullptr;
    if (!p_vout) {
        cudaFuncSetAttribute(gemm_tc, cudaFuncAttributeMaxDynamicSharedMemorySize, 39424);
        cudaGetSymbolAddress(&p_vout, d_vout);
        cudaGetSymbolAddress(&p_B, d_B);
        cudaGetSymbolAddress(&p_s, d_s);
        cudaGetSymbolAddress(&p_pooled, d_pooled);
    }

    cudaMemsetAsync(p_vout, 0, N_NODES * 128 * sizeof(float), 0);
    cudaMemsetAsync(p_B, 0, N_NODES * 128 * sizeof(float), 0);
    cudaMemsetAsync(p_s, 0, N_NODES * HEADS * sizeof(float), 0);
    cudaMemsetAsync(p_pooled, 0, 128 * sizeof(float), 0);

    prep_all<<<(PREP_TOTAL + 255) / 256, 256>>>(x, Wq, Wk, Wv, Wskip, bq, bk, bv, bskip,
                                                We);
    wqg_kernel<<<129, 128>>>(Wq, bq, We);

    // fused q|k|v|skip|g : [10000,128] @ [128,3328], 2-pass W-split bf16
    gemm_tc<<<dim3(52, 79), 256, 39168>>>(0, 0, 0, N_NODES, NQK, 128, 128);

    dim3 eblk(32, 8);
    edge_alpha<<<12500, eblk>>>(edge_attr, edge_index);
    edge_msg<<<12500, eblk>>>(edge_attr, edge_index);

    split_B<<<5000, 256>>>();
    // eterm = B @ Wer, fused relu(eterm+vout+skip) column-sum into pooled
    gemm_tc<<<dim3(2, 79), 256, 39168>>>(2, 2, 2, N_NODES, 128, 128, 128);

    final_dot<<<1, 128>>>(Wd, bd, out);
}

// round 10
// speedup vs baseline: 1.0009x; 1.0009x over previous
#include <cuda_runtime.h>
#include <cuda_bf16.h>
#include <stdint.h>
#include <math.h>

#define N_NODES 10000
#define N_EDGES 100000
#define F_NODE 128
#define F_EDGE 16
#define HEADS 8
#define OUT_CH 128
#define HC 1024
#define NQK 3328   // 1024 q | 1024 k | 1024 v | 128 skip | 128 g

// ---------------- scratch (device globals) ----------------
__device__ __nv_bfloat16 d_xh[N_NODES * 128];
__device__ __nv_bfloat16 d_qb[N_NODES * HC];
__device__ __nv_bfloat16 d_kb[N_NODES * HC];
__device__ __nv_bfloat16 d_vb[N_NODES * HC];
__device__ __nv_bfloat16 d_Bb[N_NODES * 128];
__device__ __nv_bfloat16 d_Wqh[128 * NQK];
__device__ __nv_bfloat16 d_Wql[128 * NQK];
__device__ __nv_bfloat16 d_Werh[128 * 128];
__device__ __nv_bfloat16 d_Werl[128 * 128];
__device__ float d_biasc[NQK];
__device__ float d_skip[N_NODES * 128];
__device__ float d_g[N_NODES * 128];
__device__ float d_aexp[N_EDGES * HEADS];
__device__ float d_s[N_NODES * HEADS];
__device__ float d_vout[N_NODES * 128];
__device__ float d_B[N_NODES * 128];
__device__ float d_pooled[128];

// ---------------- fused prep: bf16(x) | pack_w(h,l) | bias | wer(h,l) ----------
#define SEG0 (N_NODES * 128)
#define SEG1 (128 * 3200)
#define SEG2 (3200)
#define SEG3 (128 * 128)
#define PREP_TOTAL (SEG0 + SEG1 + SEG2 + SEG3)

__global__ __launch_bounds__(256) void prep_all(
    const float* __restrict__ x, const float* __restrict__ Wq,
    const float* __restrict__ Wk, const float* __restrict__ Wv,
    const float* __restrict__ Ws, const float* __restrict__ bq,
    const float* __restrict__ bk, const float* __restrict__ bv,
    const float* __restrict__ bs, const float* __restrict__ We) {
    int idx = blockIdx.x * 256 + threadIdx.x;
    if (idx < SEG0) {
        d_xh[idx] = __float2bfloat16(x[idx]);
        return;
    }
    idx -= SEG0;
    if (idx < SEG1) {
        int k = idx / 3200, col = idx % 3200;
        float v;
        if (col < 1024) v = Wq[k * HC + col];
        else if (col < 2048) v = Wk[k * HC + col - 1024];
        else if (col < 3072) v = Wv[k * HC + col - 2048];
        else v = Ws[k * 128 + col - 3072];
        __nv_bfloat16 h = __float2bfloat16(v);
        d_Wqh[k * NQK + col] = h;
        d_Wql[k * NQK + col] = __float2bfloat16(v - __bfloat162float(h));
        return;
    }
    idx -= SEG1;
    if (idx < SEG2) {
        float b;
        if (idx < 1024) b = bq[idx];
        else if (idx < 2048) b = bk[idx - 1024];
        else if (idx < 3072) b = bv[idx - 2048];
        else b = bs[idx - 3072];
        d_biasc[idx] = b;
        return;
    }
    idx -= SEG2;
    if (idx < SEG3) {
        int j = idx >> 7, c = idx & 127;
        int h = j >> 4, f = j & 15;
        float v = We[f * HC + h * 128 + c];
        __nv_bfloat16 hh = __float2bfloat16(v);
        d_Werh[idx] = hh;
        d_Werl[idx] = __float2bfloat16(v - __bfloat162float(hh));
    }
}

// ---------------- Wqg = Wq @ Wg (f32, folded g columns) + bg ------------------
__global__ __launch_bounds__(128) void wqg_kernel(const float* __restrict__ Wq,
                                                  const float* __restrict__ bq,
                                                  const float* __restrict__ We) {
    int b = blockIdx.x;
    int j = threadIdx.x;
    int h = j >> 4, f = j & 15;
    if (b < 128) {
        __shared__ float sq[HC];
        for (int i = j; i < HC; i += 128) sq[i] = Wq[b * HC + i];
        __syncthreads();
        const float* wep = &We[f * HC + h * 128];
        const float* qp = &sq[h * 128];
        float acc = 0.f;
#pragma unroll 8
        for (int c = 0; c < 128; c++) acc += qp[c] * wep[c];
        __nv_bfloat16 hh = __float2bfloat16(acc);
        d_Wqh[b * NQK + 3200 + j] = hh;
        d_Wql[b * NQK + 3200 + j] = __float2bfloat16(acc - __bfloat162float(hh));
    } else {
        const float* wep = &We[f * HC + h * 128];
        const float* bp = &bq[h * 128];
        float acc = 0.f;
#pragma unroll 8
        for (int c = 0; c < 128; c++) acc += bp[c] * wep[c];
        d_biasc[3200 + j] = acc;
    }
}

__global__ void split_B() {
    int i = blockIdx.x * 256 + threadIdx.x;
    if (i < N_NODES * 128) d_Bb[i] = __float2bfloat16(d_B[i]);
}

// ---------------- MMA / f32x2 helpers ----------------
__device__ __forceinline__ void ldsm4(uint32_t* r, const void* p) {
    unsigned a = (unsigned)__cvta_generic_to_shared(p);
    asm volatile("ldmatrix.sync.aligned.m8n8.x4.shared.b16 {%0,%1,%2,%3}, [%4];\n"
                 : "=r"(r[0]), "=r"(r[1]), "=r"(r[2]), "=r"(r[3]) : "r"(a));
}
__device__ __forceinline__ void ldsm4t(uint32_t* r, const void* p) {
    unsigned a = (unsigned)__cvta_generic_to_shared(p);
    asm volatile("ldmatrix.sync.aligned.m8n8.x4.trans.shared.b16 {%0,%1,%2,%3}, [%4];\n"
                 : "=r"(r[0]), "=r"(r[1]), "=r"(r[2]), "=r"(r[3]) : "r"(a));
}
__device__ __forceinline__ void mma_bf16(float* c, const uint32_t* a, uint32_t b0,
                                         uint32_t b1) {
    asm volatile(
        "mma.sync.aligned.m16n8k16.row.col.f32.bf16.bf16.f32 "
        "{%0,%1,%2,%3}, {%4,%5,%6,%7}, {%8,%9}, {%0,%1,%2,%3};\n"
        : "+f"(c[0]), "+f"(c[1]), "+f"(c[2]), "+f"(c[3])
        : "r"(a[0]), "r"(a[1]), "r"(a[2]), "r"(a[3]), "r"(b0), "r"(b1));
}
__device__ __forceinline__ void cp16(void* sdst, const void* gsrc, bool pred) {
    unsigned s = (unsigned)__cvta_generic_to_shared(sdst);
    int sz = pred ? 16 : 0;
    asm volatile("cp.async.cg.shared.global [%0], [%1], 16, %2;\n" ::"r"(s), "l"(gsrc),
                 "r"(sz));
}
__device__ __forceinline__ unsigned long long bf2f2(uint32_t u) {
    unsigned long long r;
    uint32_t lo = u << 16;
    uint32_t hi = u & 0xFFFF0000u;
    asm("mov.b64 %0, {%1,%2};" : "=l"(r) : "r"(lo), "r"(hi));
    return r;
}
__device__ __forceinline__ unsigned long long fma2(unsigned long long a,
                                                   unsigned long long b,
                                                   unsigned long long c) {
    unsigned long long d;
    asm("fma.rn.f32x2 %0, %1, %2, %3;" : "=l"(d) : "l"(a), "l"(b), "l"(c));
    return d;
}
__device__ __forceinline__ unsigned long long pack2(float x, float y) {
    unsigned long long r;
    asm("mov.b64 %0, {%1,%2};" : "=l"(r) : "f"(x), "f"(y));
    return r;
}
__device__ __forceinline__ float2 up2(unsigned long long v) {
    float2 r;
    asm("mov.b64 {%0,%1}, %2;" : "=f"(r.x), "=f"(r.y) : "l"(v));
    return r;
}

// ---------------- unified TC GEMM, double-buffered, 2-pass W-split --------------
// MT = number of 16-row m-tiles per warp (2 -> BM=128, 4 -> BM=256).
template <int MT>
__global__ __launch_bounds__(256) void gemm_tc(int asel, int wsel, int osel, int M,
                                               int N, int Kstride, int kcount) {
    constexpr int BM = MT * 64;
    const __nv_bfloat16* Ah = (asel == 0) ? d_xh : d_Bb;
    const __nv_bfloat16* Wh = (wsel == 0) ? d_Wqh : d_Werh;
    const __nv_bfloat16* Wl = (wsel == 0) ? d_Wql : d_Werl;

    extern __shared__ __align__(16) char dyn[];
    __nv_bfloat16* dynb = (__nv_bfloat16*)dyn;
    float* spool = (float*)(dyn + BM * 160 + 18432);

    int tid = threadIdx.x, w = tid >> 5, l = tid & 31;
    int bm = blockIdx.y * BM, bn = blockIdx.x * 64;
    int wm = (w >> 1) * (MT * 16), wn = (w & 1) * 32;
    if (osel == 2 && tid < 64) spool[tid] = 0.f;

    float acc[MT][4][4];
#pragma unroll
    for (int a = 0; a < MT; a++)
#pragma unroll
        for (int b = 0; b < 4; b++)
#pragma unroll
            for (int c = 0; c < 4; c++) acc[a][b][c] = 0.f;

    int a_r = (l & 7) + ((l >> 3) & 1) * 8;
    int a_ko = ((l >> 4) & 1) * 8;

    auto pA = [&](int st) { return dynb + st * (BM * 40); };
    auto pW = [&](int st, int p) { return dynb + 2 * (BM * 40) + (st * 2 + p) * 2304; };

    auto load_stage = [&](int st, int kc) {
        __nv_bfloat16* dstA = pA(st);
#pragma unroll
        for (int i = 0; i < BM / 64; i++) {
            int idx = tid + 256 * i;
            int row = idx >> 2, ch = idx & 3;
            int gr = bm + row;
            cp16(dstA + row * 40 + ch * 8, Ah + (size_t)gr * Kstride + kc + ch * 8,
                 gr < M);
        }
#pragma unroll
        for (int p = 0; p < 2; p++) {
            const __nv_bfloat16* Ws = p ? Wl : Wh;
            __nv_bfloat16* dst = pW(st, p);
            int k = tid >> 3, ch = tid & 7;
            cp16(dst + k * 72 + ch * 8, Ws + (size_t)(kc + k) * N + bn + ch * 8, true);
        }
        asm volatile("cp.async.commit_group;\n" ::);
    };

    auto compute = [&](int st) {
#pragma unroll
        for (int k16 = 0; k16 < 2; k16++) {
            uint32_t Af[MT][4], Bh[2][4], Bl[2][4];
            __nv_bfloat16* ah = pA(st);
#pragma unroll
            for (int mt = 0; mt < MT; mt++)
                ldsm4(Af[mt], ah + (wm + mt * 16 + a_r) * 40 + k16 * 16 + a_ko);
            __nv_bfloat16* wh = pW(st, 0);
            __nv_bfloat16* wl = pW(st, 1);
#pragma unroll
            for (int p = 0; p < 2; p++) {
                ldsm4t(Bh[p], wh + (k16 * 16 + a_r) * 72 + wn + p * 16 + a_ko);
                ldsm4t(Bl[p], wl + (k16 * 16 + a_r) * 72 + wn + p * 16 + a_ko);
            }
#pragma unroll
            for (int nt = 0; nt < 4; nt++) {
                uint32_t bh0 = Bh[nt >> 1][(nt & 1) * 2], bh1 = Bh[nt >> 1][(nt & 1) * 2 + 1];
                uint32_t bl0 = Bl[nt >> 1][(nt & 1) * 2], bl1 = Bl[nt >> 1][(nt & 1) * 2 + 1];
#pragma unroll
                for (int mt = 0; mt < MT; mt++) {
                    mma_bf16(acc[mt][nt], Af[mt], bh0, bh1);
                    mma_bf16(acc[mt][nt], Af[mt], bl0, bl1);
                }
            }
        }
    };

    int nIter = kcount >> 5;
    load_stage(0, 0);
    for (int it = 0; it < nIter; it++) {
        if (it + 1 < nIter) {
            load_stage((it + 1) & 1, (it + 1) * 32);
            asm volatile("cp.async.wait_group 1;\n" ::);
        } else {
            asm volatile("cp.async.wait_group 0;\n" ::);
        }
        __syncthreads();
        compute(it & 1);
        __syncthreads();
    }

    int r0 = l >> 2, cq = (l & 3) * 2;
    if (osel == 0) {
        __nv_bfloat16* dstb = nullptr;
        float* dstf = nullptr;
        int coff;
        if (bn < 1024) { dstb = d_qb; coff = bn; }
        else if (bn < 2048) { dstb = d_kb; coff = bn - 1024; }
        else if (bn < 3072) { dstb = d_vb; coff = bn - 2048; }
        else if (bn < 3200) { dstf = d_skip; coff = bn - 3072; }
        else { dstf = d_g; coff = bn - 3200; }
#pragma unroll
        for (int mt = 0; mt < MT; mt++)
#pragma unroll
            for (int nt = 0; nt < 4; nt++) {
                int gcol = bn + wn + nt * 8 + cq;
                int col = coff + wn + nt * 8 + cq;
                float bb0 = d_biasc[gcol], bb1 = d_biasc[gcol + 1];
#pragma unroll
                for (int rr = 0; rr < 2; rr++) {
                    int row = bm + wm + mt * 16 + r0 + rr * 8;
                    if (row < M) {
                        float v0 = acc[mt][nt][rr * 2] + bb0;
                        float v1 = acc[mt][nt][rr * 2 + 1] + bb1;
                        if (dstf) {
                            dstf[row * 128 + col] = v0;
                            dstf[row * 128 + col + 1] = v1;
                        } else {
                            *(__nv_bfloat162*)&dstb[(size_t)row * HC + col] =
                                __floats2bfloat162_rn(v0, v1);
                        }
                    }
                }
            }
    } else {
#pragma unroll
        for (int nt = 0; nt < 4; nt++) {
            int col = bn + wn + nt * 8 + cq;
            float s0 = 0.f, s1 = 0.f;
#pragma unroll
            for (int mt = 0; mt < MT; mt++)
#pragma unroll
                for (int rr = 0; rr < 2; rr++) {
                    int row = bm + wm + mt * 16 + r0 + rr * 8;
                    if (row < M) {
                        s0 += fmaxf(acc[mt][nt][rr * 2] + d_vout[row * 128 + col] +
                                        d_skip[row * 128 + col], 0.f);
                        s1 += fmaxf(acc[mt][nt][rr * 2 + 1] + d_vout[row * 128 + col + 1] +
                                        d_skip[row * 128 + col + 1], 0.f);
                    }
                }
#pragma unroll
            for (int off = 16; off >= 4; off >>= 1) {
                s0 += __shfl_xor_sync(0xffffffffu, s0, off);
                s1 += __shfl_xor_sync(0xffffffffu, s1, off);
            }
            if (l < 4) {
                atomicAdd(&spool[wn + nt * 8 + cq], s0);
                atomicAdd(&spool[wn + nt * 8 + cq + 1], s1);
            }
        }
        __syncthreads();
        if (tid < 64) atomicAdd(&d_pooled[bn + tid], spool[tid]);
    }
}

// ---------------- edge pass A: alpha, coalesced + f32x2 (R9-exact) --------------
__global__ __launch_bounds__(256) void edge_alpha(const float* __restrict__ ea,
                                                  const int* __restrict__ eidx) {
    int e = blockIdx.x * 8 + threadIdx.y;
    if (e >= N_EDGES) return;
    int l = threadIdx.x;
    int src = __ldg(&eidx[e]);
    int dst = __ldg(&eidx[N_EDGES + e]);
    const __nv_bfloat16* qp = &d_qb[(size_t)dst * HC + l * 8];
    const __nv_bfloat16* kp = &d_kb[(size_t)src * HC + l * 8];
    float pd[4];
#pragma unroll
    for (int j = 0; j < 4; j++) {
        uint4 qa = *(const uint4*)(qp + j * 256);
        uint4 kb = *(const uint4*)(kp + j * 256);
        unsigned long long a = 0ull;
        a = fma2(bf2f2(qa.x), bf2f2(kb.x), a);
        a = fma2(bf2f2(qa.y), bf2f2(kb.y), a);
        a = fma2(bf2f2(qa.z), bf2f2(kb.z), a);
        a = fma2(bf2f2(qa.w), bf2f2(kb.w), a);
        float2 t = up2(a);
        pd[j] = t.x + t.y;
    }
#pragma unroll
    for (int off = 1; off <= 8; off <<= 1) {
        pd[0] += __shfl_xor_sync(0xffffffffu, pd[0], off);
        pd[1] += __shfl_xor_sync(0xffffffffu, pd[1], off);
        pd[2] += __shfl_xor_sync(0xffffffffu, pd[2], off);
        pd[3] += __shfl_xor_sync(0xffffffffu, pd[3], off);
    }
    float4 g4 = *(const float4*)&d_g[dst * 128 + l * 4];
    float4 e4 = *(const float4*)&ea[e * F_EDGE + (l & 3) * 4];
    float et = g4.x * e4.x + g4.y * e4.y + g4.z * e4.z + g4.w * e4.w;
    et += __shfl_xor_sync(0xffffffffu, et, 1);
    et += __shfl_xor_sync(0xffffffffu, et, 2);
    int hsrc = (l & 1) * 16;
    float kd0 = __shfl_sync(0xffffffffu, pd[0], hsrc);
    float kd1 = __shfl_sync(0xffffffffu, pd[1], hsrc);
    float kd2 = __shfl_sync(0xffffffffu, pd[2], hsrc);
    float kd3 = __shfl_sync(0xffffffffu, pd[3], hsrc);
    float etl = __shfl_sync(0xffffffffu, et, (l & 7) * 4);
    if (l < 8) {
        int jj = l >> 1;
        float kd = (jj == 0) ? kd0 : (jj == 1) ? kd1 : (jj == 2) ? kd2 : kd3;
        float aex = __expf((kd + etl) * 0.08838834764831845f);
        d_aexp[e * 8 + l] = aex;
        atomicAdd(&d_s[dst * 8 + l], aex);
    }
}

// ---------------- edge pass B: v-term + B scatter, f32x2 (R9-exact) -------------
__global__ __launch_bounds__(256) void edge_msg(const float* __restrict__ ea,
                                                const int* __restrict__ eidx) {
    int e = blockIdx.x * 8 + threadIdx.y;
    if (e >= N_EDGES) return;
    int l = threadIdx.x;
    int src = __ldg(&eidx[e]);
    int dst = __ldg(&eidx[N_EDGES + e]);
    float an = 0.f;
    if (l < 8) {
        float s = d_s[dst * 8 + l];
        an = 0.125f * d_aexp[e * 8 + l] / (s + 1e-16f);
    }
    int h2 = l >> 4, c8 = l & 15;
    unsigned long long acc2[4] = {0ull, 0ull, 0ull, 0ull};
#pragma unroll
    for (int hh = 0; hh < 4; hh++) {
        int h = h2 * 4 + hh;
        float anh = __shfl_sync(0xffffffffu, an, h);
        unsigned long long an2 = pack2(anh, anh);
        uint4 vv = *(const uint4*)&d_vb[(size_t)src * HC + h * 128 + c8 * 8];
        acc2[0] = fma2(bf2f2(vv.x), an2, acc2[0]);
        acc2[1] = fma2(bf2f2(vv.y), an2, acc2[1]);
        acc2[2] = fma2(bf2f2(vv.z), an2, acc2[2]);
        acc2[3] = fma2(bf2f2(vv.w), an2, acc2[3]);
    }
    float acc[8];
#pragma unroll
    for (int j = 0; j < 4; j++) {
        float2 t = up2(acc2[j]);
        acc[j * 2] = t.x;
        acc[j * 2 + 1] = t.y;
    }
#pragma unroll
    for (int j = 0; j < 8; j++) acc[j] += __shfl_xor_sync(0xffffffffu, acc[j], 16);
    if (h2 == 0) {
        float* outp = &d_vout[dst * 128 + c8 * 8];
        asm volatile("red.global.add.v4.f32 [%0], {%1,%2,%3,%4};\n" ::"l"(outp),
                     "f"(acc[0]), "f"(acc[1]), "f"(acc[2]), "f"(acc[3])
                     : "memory");
        asm volatile("red.global.add.v4.f32 [%0], {%1,%2,%3,%4};\n" ::"l"(outp + 4),
                     "f"(acc[4]), "f"(acc[5]), "f"(acc[6]), "f"(acc[7])
                     : "memory");
    }
    float4 ea4 = ((const float4*)&ea[e * F_EDGE])[l & 3];
    float anj = __shfl_sync(0xffffffffu, an, l >> 2);
    float* bp = &d_B[dst * 128 + l * 4];
    asm volatile("red.global.add.v4.f32 [%0], {%1,%2,%3,%4};\n" ::"l"(bp),
                 "f"(anj * ea4.x), "f"(anj * ea4.y), "f"(anj * ea4.z), "f"(anj * ea4.w)
                 : "memory");
}

// ---------------- final dot ----------------
__global__ __launch_bounds__(128) void final_dot(const float* __restrict__ Wd,
                                                 const float* __restrict__ bd,
                                                 float* __restrict__ out) {
    int t = threadIdx.x;
    float v = d_pooled[t] * Wd[t];
#pragma unroll
    for (int o = 16; o; o >>= 1) v += __shfl_xor_sync(0xffffffffu, v, o);
    __shared__ float red[4];
    if ((t & 31) == 0) red[t >> 5] = v;
    __syncthreads();
    if (t == 0) out[0] = red[0] + red[1] + red[2] + red[3] + bd[0];
}

extern "C" void kernel_launch(void* const* d_in, const int* in_sizes, int n_in,
                              void* d_out, int out_size) {
    const float* x          = (const float*)d_in[0];
    const float* edge_attr  = (const float*)d_in[1];
    const int*   edge_index = (const int*)d_in[2];
    const float* Wq = (const float*)d_in[3];
    const float* bq = (const float*)d_in[4];
    const float* Wk = (const float*)d_in[5];
    const float* bk = (const float*)d_in[6];
    const float* Wv = (const float*)d_in[7];
    const float* bv = (const float*)d_in[8];
    const float* We = (const float*)d_in[9];
    const float* Wskip = (const float*)d_in[10];
    const float* bskip = (const float*)d_in[11];
    const float* Wd = (const float*)d_in[12];
    const float* bd = (const float*)d_in[13];
    float* out = (float*)d_out;

    static void *p_vout = nullptr, *p_B = nullptr, *p_s = nullptr, *p_pooled = nullptr;
    if (!p_vout) {
        cudaFuncSetAttribute(gemm_tc<4>, cudaFuncAttributeMaxDynamicSharedMemorySize,
                             60416);
        cudaFuncSetAttribute(gemm_tc<2>, cudaFuncAttributeMaxDynamicSharedMemorySize,
                             39424);
        cudaGetSymbolAddress(&p_vout, d_vout);
        cudaGetSymbolAddress(&p_B, d_B);
        cudaGetSymbolAddress(&p_s, d_s);
        cudaGetSymbolAddress(&p_pooled, d_pooled);
    }

    cudaMemsetAsync(p_vout, 0, N_NODES * 128 * sizeof(float), 0);
    cudaMemsetAsync(p_B, 0, N_NODES * 128 * sizeof(float), 0);
    cudaMemsetAsync(p_s, 0, N_NODES * HEADS * sizeof(float), 0);
    cudaMemsetAsync(p_pooled, 0, 128 * sizeof(float), 0);

    prep_all<<<(PREP_TOTAL + 255) / 256, 256>>>(x, Wq, Wk, Wv, Wskip, bq, bk, bv, bskip,
                                                We);
    wqg_kernel<<<129, 128>>>(Wq, bq, We);

    // fused q|k|v|skip|g : [10000,128] @ [128,3328], 2-pass W-split, BM=256
    gemm_tc<4><<<dim3(52, 40), 256, 59648>>>(0, 0, 0, N_NODES, NQK, 128, 128);

    dim3 eblk(32, 8);
    edge_alpha<<<12500, eblk>>>(edge_attr, edge_index);
    edge_msg<<<12500, eblk>>>(edge_attr, edge_index);

    split_B<<<5000, 256>>>();
    // eterm = B @ Wer, fused relu(eterm+vout+skip) column-sum into pooled, BM=128
    gemm_tc<2><<<dim3(2, 79), 256, 39168>>>(2, 2, 2, N_NODES, 128, 128, 128);

    final_dot<<<1, 128>>>(Wd, bd, out);
}

// round 11
// speedup vs baseline: 1.0339x; 1.0330x over previous
#include <cuda_runtime.h>
#include <cuda_bf16.h>
#include <stdint.h>
#include <math.h>

#define N_NODES 10000
#define N_EDGES 100000
#define F_NODE 128
#define F_EDGE 16
#define HEADS 8
#define OUT_CH 128
#define HC 1024
#define NQK 3328   // 1024 q | 1024 k | 1024 v | 128 skip | 128 g

// ---------------- scratch (device globals) ----------------
__device__ __nv_bfloat16 d_xh[N_NODES * 128];
__device__ __nv_bfloat16 d_qb[N_NODES * HC];
__device__ __nv_bfloat16 d_kb[N_NODES * HC];
__device__ __nv_bfloat16 d_vb[N_NODES * HC];
__device__ __nv_bfloat16 d_Wqh[128 * NQK];
__device__ __nv_bfloat16 d_Wql[128 * NQK];
__device__ __nv_bfloat16 d_Werh[128 * 128];
__device__ __nv_bfloat16 d_Werl[128 * 128];
__device__ float d_biasc[NQK];
__device__ float d_skip[N_NODES * 128];
__device__ float d_g[N_NODES * 128];
__device__ float d_aexp[N_EDGES * HEADS];
__device__ float d_s[N_NODES * HEADS];
__device__ float d_vout[N_NODES * 128];
__device__ float d_B[N_NODES * 128];
__device__ float d_pooled[128];

// ---------------- fused prep: bf16(x) | pack_w(h,l) | bias | wer(h,l) ----------
#define SEG0 (N_NODES * 128)
#define SEG1 (128 * 3200)
#define SEG2 (3200)
#define SEG3 (128 * 128)
#define PREP_TOTAL (SEG0 + SEG1 + SEG2 + SEG3)

__global__ __launch_bounds__(256) void prep_all(
    const float* __restrict__ x, const float* __restrict__ Wq,
    const float* __restrict__ Wk, const float* __restrict__ Wv,
    const float* __restrict__ Ws, const float* __restrict__ bq,
    const float* __restrict__ bk, const float* __restrict__ bv,
    const float* __restrict__ bs, const float* __restrict__ We) {
    int idx = blockIdx.x * 256 + threadIdx.x;
    if (idx < SEG0) {
        d_xh[idx] = __float2bfloat16(x[idx]);
        return;
    }
    idx -= SEG0;
    if (idx < SEG1) {
        int k = idx / 3200, col = idx % 3200;
        float v;
        if (col < 1024) v = Wq[k * HC + col];
        else if (col < 2048) v = Wk[k * HC + col - 1024];
        else if (col < 3072) v = Wv[k * HC + col - 2048];
        else v = Ws[k * 128 + col - 3072];
        __nv_bfloat16 h = __float2bfloat16(v);
        d_Wqh[k * NQK + col] = h;
        d_Wql[k * NQK + col] = __float2bfloat16(v - __bfloat162float(h));
        return;
    }
    idx -= SEG1;
    if (idx < SEG2) {
        float b;
        if (idx < 1024) b = bq[idx];
        else if (idx < 2048) b = bk[idx - 1024];
        else if (idx < 3072) b = bv[idx - 2048];
        else b = bs[idx - 3072];
        d_biasc[idx] = b;
        return;
    }
    idx -= SEG2;
    if (idx < SEG3) {
        int j = idx >> 7, c = idx & 127;
        int h = j >> 4, f = j & 15;
        float v = We[f * HC + h * 128 + c];
        __nv_bfloat16 hh = __float2bfloat16(v);
        d_Werh[idx] = hh;
        d_Werl[idx] = __float2bfloat16(v - __bfloat162float(hh));
    }
}

// ---------------- Wqg = Wq @ Wg (f32, folded g columns) + bg ------------------
__global__ __launch_bounds__(128) void wqg_kernel(const float* __restrict__ Wq,
                                                  const float* __restrict__ bq,
                                                  const float* __restrict__ We) {
    int b = blockIdx.x;
    int j = threadIdx.x;
    int h = j >> 4, f = j & 15;
    if (b < 128) {
        __shared__ float sq[HC];
        for (int i = j; i < HC; i += 128) sq[i] = Wq[b * HC + i];
        __syncthreads();
        const float* wep = &We[f * HC + h * 128];
        const float* qp = &sq[h * 128];
        float acc = 0.f;
#pragma unroll 8
        for (int c = 0; c < 128; c++) acc += qp[c] * wep[c];
        __nv_bfloat16 hh = __float2bfloat16(acc);
        d_Wqh[b * NQK + 3200 + j] = hh;
        d_Wql[b * NQK + 3200 + j] = __float2bfloat16(acc - __bfloat162float(hh));
    } else {
        const float* wep = &We[f * HC + h * 128];
        const float* bp = &bq[h * 128];
        float acc = 0.f;
#pragma unroll 8
        for (int c = 0; c < 128; c++) acc += bp[c] * wep[c];
        d_biasc[3200 + j] = acc;
    }
}

// ---------------- MMA / f32x2 helpers ----------------
__device__ __forceinline__ void ldsm4(uint32_t* r, const void* p) {
    unsigned a = (unsigned)__cvta_generic_to_shared(p);
    asm volatile("ldmatrix.sync.aligned.m8n8.x4.shared.b16 {%0,%1,%2,%3}, [%4];\n"
                 : "=r"(r[0]), "=r"(r[1]), "=r"(r[2]), "=r"(r[3]) : "r"(a));
}
__device__ __forceinline__ void ldsm4t(uint32_t* r, const void* p) {
    unsigned a = (unsigned)__cvta_generic_to_shared(p);
    asm volatile("ldmatrix.sync.aligned.m8n8.x4.trans.shared.b16 {%0,%1,%2,%3}, [%4];\n"
                 : "=r"(r[0]), "=r"(r[1]), "=r"(r[2]), "=r"(r[3]) : "r"(a));
}
__device__ __forceinline__ void mma_bf16(float* c, const uint32_t* a, uint32_t b0,
                                         uint32_t b1) {
    asm volatile(
        "mma.sync.aligned.m16n8k16.row.col.f32.bf16.bf16.f32 "
        "{%0,%1,%2,%3}, {%4,%5,%6,%7}, {%8,%9}, {%0,%1,%2,%3};\n"
        : "+f"(c[0]), "+f"(c[1]), "+f"(c[2]), "+f"(c[3])
        : "r"(a[0]), "r"(a[1]), "r"(a[2]), "r"(a[3]), "r"(b0), "r"(b1));
}
__device__ __forceinline__ void cp16(void* sdst, const void* gsrc, bool pred) {
    unsigned s = (unsigned)__cvta_generic_to_shared(sdst);
    int sz = pred ? 16 : 0;
    asm volatile("cp.async.cg.shared.global [%0], [%1], 16, %2;\n" ::"r"(s), "l"(gsrc),
                 "r"(sz));
}
__device__ __forceinline__ unsigned long long bf2f2(uint32_t u) {
    unsigned long long r;
    uint32_t lo = u << 16;
    uint32_t hi = u & 0xFFFF0000u;
    asm("mov.b64 %0, {%1,%2};" : "=l"(r) : "r"(lo), "r"(hi));
    return r;
}
__device__ __forceinline__ unsigned long long fma2(unsigned long long a,
                                                   unsigned long long b,
                                                   unsigned long long c) {
    unsigned long long d;
    asm("fma.rn.f32x2 %0, %1, %2, %3;" : "=l"(d) : "l"(a), "l"(b), "l"(c));
    return d;
}
__device__ __forceinline__ unsigned long long pack2(float x, float y) {
    unsigned long long r;
    asm("mov.b64 %0, {%1,%2};" : "=l"(r) : "f"(x), "f"(y));
    return r;
}
__device__ __forceinline__ float2 up2(unsigned long long v) {
    float2 r;
    asm("mov.b64 {%0,%1}, %2;" : "=f"(r.x), "=f"(r.y) : "l"(v));
    return r;
}
__device__ __forceinline__ uint32_t pkbf(float a, float b) {
    __nv_bfloat162 t = __floats2bfloat162_rn(a, b);
    return *(uint32_t*)&t;
}

// ---------------- unified TC GEMM, double-buffered, 2-pass W-split --------------
// MT: 16-row m-tiles per warp (2 -> BM=128, 4 -> BM=256).
// asel: 0 = d_xh (bf16); 2 = d_B (f32, converted inline).
// wsel: 0 = packed Wqkvsg; 2 = Wer.  osel: 0 = region stores; 2 = fused reduce.
// bnmode: 0 bn=bx*64 | 1 part1 (q,k then g) | 2 part2 (v,skip)
template <int MT>
__global__ __launch_bounds__(256) void gemm_tc(int asel, int wsel, int osel, int bnmode,
                                               int M, int N, int Kstride, int kcount) {
    constexpr int BM = MT * 64;
    const __nv_bfloat16* Wh = (wsel == 0) ? d_Wqh : d_Werh;
    const __nv_bfloat16* Wl = (wsel == 0) ? d_Wql : d_Werl;

    extern __shared__ __align__(16) char dyn[];
    __nv_bfloat16* dynb = (__nv_bfloat16*)dyn;
    float* spool = (float*)(dyn + BM * 160 + 18432);

    int tid = threadIdx.x, w = tid >> 5, l = tid & 31;
    int bx = blockIdx.x;
    int bn;
    if (bnmode == 1) bn = (bx < 32) ? bx * 64 : 3200 + (bx - 32) * 64;
    else if (bnmode == 2) bn = 2048 + bx * 64;
    else bn = bx * 64;
    int bm = blockIdx.y * BM;
    int wm = (w >> 1) * (MT * 16), wn = (w & 1) * 32;
    if (osel == 2 && tid < 64) spool[tid] = 0.f;

    float acc[MT][4][4];
#pragma unroll
    for (int a = 0; a < MT; a++)
#pragma unroll
        for (int b = 0; b < 4; b++)
#pragma unroll
            for (int c = 0; c < 4; c++) acc[a][b][c] = 0.f;

    int a_r = (l & 7) + ((l >> 3) & 1) * 8;
    int a_ko = ((l >> 4) & 1) * 8;

    auto pA = [&](int st) { return dynb + st * (BM * 40); };
    auto pW = [&](int st, int p) { return dynb + 2 * (BM * 40) + (st * 2 + p) * 2304; };

    auto load_stage = [&](int st, int kc) {
        __nv_bfloat16* dstA = pA(st);
        if (asel == 0) {
#pragma unroll
            for (int i = 0; i < BM / 64; i++) {
                int idx = tid + 256 * i;
                int row = idx >> 2, ch = idx & 3;
                int gr = bm + row;
                cp16(dstA + row * 40 + ch * 8, d_xh + (size_t)gr * Kstride + kc + ch * 8,
                     gr < M);
            }
        } else {
            // A = d_B (f32) -> convert to bf16 inline
#pragma unroll
            for (int i = 0; i < BM / 64; i++) {
                int idx = tid + 256 * i;
                int row = idx >> 2, ch = idx & 3;
                int gr = bm + row;
                float4 f0 = make_float4(0.f, 0.f, 0.f, 0.f), f1 = f0;
                if (gr < M) {
                    const float4* sp = (const float4*)&d_B[(size_t)gr * 128 + kc + ch * 8];
                    f0 = sp[0];
                    f1 = sp[1];
                }
                uint4 u;
                u.x = pkbf(f0.x, f0.y);
                u.y = pkbf(f0.z, f0.w);
                u.z = pkbf(f1.x, f1.y);
                u.w = pkbf(f1.z, f1.w);
                *(uint4*)(dstA + row * 40 + ch * 8) = u;
            }
        }
#pragma unroll
        for (int p = 0; p < 2; p++) {
            const __nv_bfloat16* Ws = p ? Wl : Wh;
            __nv_bfloat16* dst = pW(st, p);
            int k = tid >> 3, ch = tid & 7;
            cp16(dst + k * 72 + ch * 8, Ws + (size_t)(kc + k) * N + bn + ch * 8, true);
        }
        asm volatile("cp.async.commit_group;\n" ::);
    };

    auto compute = [&](int st) {
#pragma unroll
        for (int k16 = 0; k16 < 2; k16++) {
            uint32_t Af[MT][4], Bh[2][4], Bl[2][4];
            __nv_bfloat16* ah = pA(st);
#pragma unroll
            for (int mt = 0; mt < MT; mt++)
                ldsm4(Af[mt], ah + (wm + mt * 16 + a_r) * 40 + k16 * 16 + a_ko);
            __nv_bfloat16* wh = pW(st, 0);
            __nv_bfloat16* wl = pW(st, 1);
#pragma unroll
            for (int p = 0; p < 2; p++) {
                ldsm4t(Bh[p], wh + (k16 * 16 + a_r) * 72 + wn + p * 16 + a_ko);
                ldsm4t(Bl[p], wl + (k16 * 16 + a_r) * 72 + wn + p * 16 + a_ko);
            }
#pragma unroll
            for (int nt = 0; nt < 4; nt++) {
                uint32_t bh0 = Bh[nt >> 1][(nt & 1) * 2], bh1 = Bh[nt >> 1][(nt & 1) * 2 + 1];
                uint32_t bl0 = Bl[nt >> 1][(nt & 1) * 2], bl1 = Bl[nt >> 1][(nt & 1) * 2 + 1];
#pragma unroll
                for (int mt = 0; mt < MT; mt++) {
                    mma_bf16(acc[mt][nt], Af[mt], bh0, bh1);
                    mma_bf16(acc[mt][nt], Af[mt], bl0, bl1);
                }
            }
        }
    };

    int nIter = kcount >> 5;
    load_stage(0, 0);
    for (int it = 0; it < nIter; it++) {
        if (it + 1 < nIter) {
            load_stage((it + 1) & 1, (it + 1) * 32);
            asm volatile("cp.async.wait_group 1;\n" ::);
        } else {
            asm volatile("cp.async.wait_group 0;\n" ::);
        }
        __syncthreads();
        compute(it & 1);
        __syncthreads();
    }

    int r0 = l >> 2, cq = (l & 3) * 2;
    if (osel == 0) {
        __nv_bfloat16* dstb = nullptr;
        float* dstf = nullptr;
        int coff;
        if (bn < 1024) { dstb = d_qb; coff = bn; }
        else if (bn < 2048) { dstb = d_kb; coff = bn - 1024; }
        else if (bn < 3072) { dstb = d_vb; coff = bn - 2048; }
        else if (bn < 3200) { dstf = d_skip; coff = bn - 3072; }
        else { dstf = d_g; coff = bn - 3200; }
#pragma unroll
        for (int mt = 0; mt < MT; mt++)
#pragma unroll
            for (int nt = 0; nt < 4; nt++) {
                int gcol = bn + wn + nt * 8 + cq;
                int col = coff + wn + nt * 8 + cq;
                float bb0 = d_biasc[gcol], bb1 = d_biasc[gcol + 1];
#pragma unroll
                for (int rr = 0; rr < 2; rr++) {
                    int row = bm + wm + mt * 16 + r0 + rr * 8;
                    if (row < M) {
                        float v0 = acc[mt][nt][rr * 2] + bb0;
                        float v1 = acc[mt][nt][rr * 2 + 1] + bb1;
                        if (dstf) {
                            dstf[row * 128 + col] = v0;
                            dstf[row * 128 + col + 1] = v1;
                        } else {
                            *(__nv_bfloat162*)&dstb[(size_t)row * HC + col] =
                                __floats2bfloat162_rn(v0, v1);
                        }
                    }
                }
            }
    } else {
#pragma unroll
        for (int nt = 0; nt < 4; nt++) {
            int col = bn + wn + nt * 8 + cq;
            float s0 = 0.f, s1 = 0.f;
#pragma unroll
            for (int mt = 0; mt < MT; mt++)
#pragma unroll
                for (int rr = 0; rr < 2; rr++) {
                    int row = bm + wm + mt * 16 + r0 + rr * 8;
                    if (row < M) {
                        s0 += fmaxf(acc[mt][nt][rr * 2] + d_vout[row * 128 + col] +
                                        d_skip[row * 128 + col], 0.f);
                        s1 += fmaxf(acc[mt][nt][rr * 2 + 1] + d_vout[row * 128 + col + 1] +
                                        d_skip[row * 128 + col + 1], 0.f);
                    }
                }
#pragma unroll
            for (int off = 16; off >= 4; off >>= 1) {
                s0 += __shfl_xor_sync(0xffffffffu, s0, off);
                s1 += __shfl_xor_sync(0xffffffffu, s1, off);
            }
            if (l < 4) {
                atomicAdd(&spool[wn + nt * 8 + cq], s0);
                atomicAdd(&spool[wn + nt * 8 + cq + 1], s1);
            }
        }
        __syncthreads();
        if (tid < 64) atomicAdd(&d_pooled[bn + tid], spool[tid]);
    }
}

// ---------------- edge pass A: alpha, coalesced + f32x2 (R9-exact) --------------
__global__ __launch_bounds__(256) void edge_alpha(const float* __restrict__ ea,
                                                  const int* __restrict__ eidx) {
    int e = blockIdx.x * 8 + threadIdx.y;
    if (e >= N_EDGES) return;
    int l = threadIdx.x;
    int src = __ldg(&eidx[e]);
    int dst = __ldg(&eidx[N_EDGES + e]);
    const __nv_bfloat16* qp = &d_qb[(size_t)dst * HC + l * 8];
    const __nv_bfloat16* kp = &d_kb[(size_t)src * HC + l * 8];
    float pd[4];
#pragma unroll
    for (int j = 0; j < 4; j++) {
        uint4 qa = *(const uint4*)(qp + j * 256);
        uint4 kb = *(const uint4*)(kp + j * 256);
        unsigned long long a = 0ull;
        a = fma2(bf2f2(qa.x), bf2f2(kb.x), a);
        a = fma2(bf2f2(qa.y), bf2f2(kb.y), a);
        a = fma2(bf2f2(qa.z), bf2f2(kb.z), a);
        a = fma2(bf2f2(qa.w), bf2f2(kb.w), a);
        float2 t = up2(a);
        pd[j] = t.x + t.y;
    }
#pragma unroll
    for (int off = 1; off <= 8; off <<= 1) {
        pd[0] += __shfl_xor_sync(0xffffffffu, pd[0], off);
        pd[1] += __shfl_xor_sync(0xffffffffu, pd[1], off);
        pd[2] += __shfl_xor_sync(0xffffffffu, pd[2], off);
        pd[3] += __shfl_xor_sync(0xffffffffu, pd[3], off);
    }
    float4 g4 = *(const float4*)&d_g[dst * 128 + l * 4];
    float4 e4 = *(const float4*)&ea[e * F_EDGE + (l & 3) * 4];
    float et = g4.x * e4.x + g4.y * e4.y + g4.z * e4.z + g4.w * e4.w;
    et += __shfl_xor_sync(0xffffffffu, et, 1);
    et += __shfl_xor_sync(0xffffffffu, et, 2);
    int hsrc = (l & 1) * 16;
    float kd0 = __shfl_sync(0xffffffffu, pd[0], hsrc);
    float kd1 = __shfl_sync(0xffffffffu, pd[1], hsrc);
    float kd2 = __shfl_sync(0xffffffffu, pd[2], hsrc);
    float kd3 = __shfl_sync(0xffffffffu, pd[3], hsrc);
    float etl = __shfl_sync(0xffffffffu, et, (l & 7) * 4);
    if (l < 8) {
        int jj = l >> 1;
        float kd = (jj == 0) ? kd0 : (jj == 1) ? kd1 : (jj == 2) ? kd2 : kd3;
        float aex = __expf((kd + etl) * 0.08838834764831845f);
        d_aexp[e * 8 + l] = aex;
        atomicAdd(&d_s[dst * 8 + l], aex);
    }
}

// ---------------- edge pass B: v-term + B scatter, f32x2 (R9-exact) -------------
__global__ __launch_bounds__(256) void edge_msg(const float* __restrict__ ea,
                                                const int* __restrict__ eidx) {
    int e = blockIdx.x * 8 + threadIdx.y;
    if (e >= N_EDGES) return;
    int l = threadIdx.x;
    int src = __ldg(&eidx[e]);
    int dst = __ldg(&eidx[N_EDGES + e]);
    float an = 0.f;
    if (l < 8) {
        float s = d_s[dst * 8 + l];
        an = 0.125f * d_aexp[e * 8 + l] / (s + 1e-16f);
    }
    int h2 = l >> 4, c8 = l & 15;
    unsigned long long acc2[4] = {0ull, 0ull, 0ull, 0ull};
#pragma unroll
    for (int hh = 0; hh < 4; hh++) {
        int h = h2 * 4 + hh;
        float anh = __shfl_sync(0xffffffffu, an, h);
        unsigned long long an2 = pack2(anh, anh);
        uint4 vv = *(const uint4*)&d_vb[(size_t)src * HC + h * 128 + c8 * 8];
        acc2[0] = fma2(bf2f2(vv.x), an2, acc2[0]);
        acc2[1] = fma2(bf2f2(vv.y), an2, acc2[1]);
        acc2[2] = fma2(bf2f2(vv.z), an2, acc2[2]);
        acc2[3] = fma2(bf2f2(vv.w), an2, acc2[3]);
    }
    float acc[8];
#pragma unroll
    for (int j = 0; j < 4; j++) {
        float2 t = up2(acc2[j]);
        acc[j * 2] = t.x;
        acc[j * 2 + 1] = t.y;
    }
#pragma unroll
    for (int j = 0; j < 8; j++) acc[j] += __shfl_xor_sync(0xffffffffu, acc[j], 16);
    if (h2 == 0) {
        float* outp = &d_vout[dst * 128 + c8 * 8];
        asm volatile("red.global.add.v4.f32 [%0], {%1,%2,%3,%4};\n" ::"l"(outp),
                     "f"(acc[0]), "f"(acc[1]), "f"(acc[2]), "f"(acc[3])
                     : "memory");
        asm volatile("red.global.add.v4.f32 [%0], {%1,%2,%3,%4};\n" ::"l"(outp + 4),
                     "f"(acc[4]), "f"(acc[5]), "f"(acc[6]), "f"(acc[7])
                     : "memory");
    }
    float4 ea4 = ((const float4*)&ea[e * F_EDGE])[l & 3];
    float anj = __shfl_sync(0xffffffffu, an, l >> 2);
    float* bp = &d_B[dst * 128 + l * 4];
    asm volatile("red.global.add.v4.f32 [%0], {%1,%2,%3,%4};\n" ::"l"(bp),
                 "f"(anj * ea4.x), "f"(anj * ea4.y), "f"(anj * ea4.z), "f"(anj * ea4.w)
                 : "memory");
}

// ---------------- final dot ----------------
__global__ __launch_bounds__(128) void final_dot(const float* __restrict__ Wd,
                                                 const float* __restrict__ bd,
                                                 float* __restrict__ out) {
    int t = threadIdx.x;
    float v = d_pooled[t] * Wd[t];
#pragma unroll
    for (int o = 16; o; o >>= 1) v += __shfl_xor_sync(0xffffffffu, v, o);
    __shared__ float red[4];
    if ((t & 31) == 0) red[t >> 5] = v;
    __syncthreads();
    if (t == 0) out[0] = red[0] + red[1] + red[2] + red[3] + bd[0];
}

extern "C" void kernel_launch(void* const* d_in, const int* in_sizes, int n_in,
                              void* d_out, int out_size) {
    const float* x          = (const float*)d_in[0];
    const float* edge_attr  = (const float*)d_in[1];
    const int*   edge_index = (const int*)d_in[2];
    const float* Wq = (const float*)d_in[3];
    const float* bq = (const float*)d_in[4];
    const float* Wk = (const float*)d_in[5];
    const float* bk = (const float*)d_in[6];
    const float* Wv = (const float*)d_in[7];
    const float* bv = (const float*)d_in[8];
    const float* We = (const float*)d_in[9];
    const float* Wskip = (const float*)d_in[10];
    const float* bskip = (const float*)d_in[11];
    const float* Wd = (const float*)d_in[12];
    const float* bd = (const float*)d_in[13];
    float* out = (float*)d_out;

    static void *p_vout = nullptr, *p_B = nullptr, *p_s = nullptr, *p_pooled = nullptr;
    static cudaStream_t s2 = nullptr;
    static cudaEvent_t evA = nullptr, evB = nullptr;
    if (!p_vout) {
        cudaFuncSetAttribute(gemm_tc<4>, cudaFuncAttributeMaxDynamicSharedMemorySize,
                             60416);
        cudaFuncSetAttribute(gemm_tc<2>, cudaFuncAttributeMaxDynamicSharedMemorySize,
                             39424);
        cudaGetSymbolAddress(&p_vout, d_vout);
        cudaGetSymbolAddress(&p_B, d_B);
        cudaGetSymbolAddress(&p_s, d_s);
        cudaGetSymbolAddress(&p_pooled, d_pooled);
        cudaStreamCreateWithFlags(&s2, cudaStreamNonBlocking);
        cudaEventCreateWithFlags(&evA, cudaEventDisableTiming);
        cudaEventCreateWithFlags(&evB, cudaEventDisableTiming);
    }

    cudaMemsetAsync(p_vout, 0, N_NODES * 128 * sizeof(float), 0);
    cudaMemsetAsync(p_B, 0, N_NODES * 128 * sizeof(float), 0);
    cudaMemsetAsync(p_s, 0, N_NODES * HEADS * sizeof(float), 0);
    cudaMemsetAsync(p_pooled, 0, 128 * sizeof(float), 0);

    prep_all<<<(PREP_TOTAL + 255) / 256, 256>>>(x, Wq, Wk, Wv, Wskip, bq, bk, bv, bskip,
                                                We);
    wqg_kernel<<<129, 128>>>(Wq, bq, We);

    // part 1: q | k | g columns (needed by edge_alpha)
    gemm_tc<4><<<dim3(34, 40), 256, 59648>>>(0, 0, 0, 1, N_NODES, NQK, 128, 128);
    cudaEventRecord(evA, 0);
    // part 2: v | skip columns, forked onto s2 — overlaps edge_alpha
    cudaStreamWaitEvent(s2, evA, 0);
    gemm_tc<4><<<dim3(18, 40), 256, 59648, s2>>>(0, 0, 0, 2, N_NODES, NQK, 128, 128);
    cudaEventRecord(evB, s2);

    dim3 eblk(32, 8);
    edge_alpha<<<12500, eblk>>>(edge_attr, edge_index);

    cudaStreamWaitEvent(0, evB, 0);
    edge_msg<<<12500, eblk>>>(edge_attr, edge_index);

    // eterm = B @ Wer (A converted f32->bf16 inline), fused reduce into pooled
    gemm_tc<2><<<dim3(2, 79), 256, 39168>>>(2, 2, 2, 0, N_NODES, 128, 128, 128);

    final_dot<<<1, 128>>>(Wd, bd, out);
}